// round 2
// baseline (speedup 1.0000x reference)
#include <cuda_runtime.h>
#include <cstdint>
#include <cstddef>

// Problem constants
#define T_STEPS 512
#define BATCH   64
#define INP     512
#define HID     512
#define KTOT    1024          // I + H fused k-window
#define NCTA    128
#define NTHREADS 256
#define ROWS    16            // gate rows per CTA (4 gates * 4 H-cols)
#define BAR_PER_LAUNCH ((unsigned long long)T_STEPS * NCTA)

// smem: Ws[16][1024] | bias[16] | G[16][64]
#define SMEM_FLOATS (ROWS*KTOT + ROWS + ROWS*BATCH)
#define SMEM_BYTES  (SMEM_FLOATS * 4)

__device__ unsigned long long g_bar = 0ULL;

__device__ __forceinline__ unsigned long long ld_vol_u64(const unsigned long long* p) {
    unsigned long long v;
    asm volatile("ld.volatile.global.u64 %0, [%1];" : "=l"(v) : "l"(p));
    return v;
}

// One 128-k iteration of the fused GEMM for this warp.
// a0: activation base for (batch b0, this lane's k)  [row stride 512 floats]
// wb: smem weight base for (row r0, this lane's k)   [row stride 1024 floats]
__device__ __forceinline__ void do_iter_x(const float* __restrict__ a0,
                                          const float* __restrict__ wb,
                                          float (&red)[128]) {
    float4 w4[8];
    #pragma unroll
    for (int r = 0; r < 8; r++) w4[r] = *(const float4*)(wb + r * KTOT);
    #pragma unroll
    for (int half = 0; half < 2; half++) {
        float4 ab[8];
        #pragma unroll
        for (int b = 0; b < 8; b++)
            ab[b] = __ldg((const float4*)(a0 + (size_t)(half * 8 + b) * INP));
        #pragma unroll
        for (int b = 0; b < 8; b++) {
            const int bi = half * 8 + b;
            const float4 a = ab[b];
            #pragma unroll
            for (int r = 0; r < 8; r++) {
                const float4 w = w4[r];
                red[bi * 8 + r] = fmaf(a.x, w.x,
                                   fmaf(a.y, w.y,
                                    fmaf(a.z, w.z,
                                     fmaf(a.w, w.w, red[bi * 8 + r]))));
            }
        }
    }
}

// Same but activations loaded L2-only (h crosses the grid barrier each step).
__device__ __forceinline__ void do_iter_h(const float* __restrict__ a0,
                                          const float* __restrict__ wb,
                                          float (&red)[128]) {
    float4 w4[8];
    #pragma unroll
    for (int r = 0; r < 8; r++) w4[r] = *(const float4*)(wb + r * KTOT);
    #pragma unroll
    for (int half = 0; half < 2; half++) {
        float4 ab[8];
        #pragma unroll
        for (int b = 0; b < 8; b++)
            ab[b] = __ldcg((const float4*)(a0 + (size_t)(half * 8 + b) * HID));
        #pragma unroll
        for (int b = 0; b < 8; b++) {
            const int bi = half * 8 + b;
            const float4 a = ab[b];
            #pragma unroll
            for (int r = 0; r < 8; r++) {
                const float4 w = w4[r];
                red[bi * 8 + r] = fmaf(a.x, w.x,
                                   fmaf(a.y, w.y,
                                    fmaf(a.z, w.z,
                                     fmaf(a.w, w.w, red[bi * 8 + r]))));
            }
        }
    }
}

__global__ void __launch_bounds__(NTHREADS, 1)
lstm_persistent(const float* __restrict__ x,
                const float* __restrict__ W_ih,
                const float* __restrict__ W_hh,
                const float* __restrict__ b_ih,
                const float* __restrict__ b_hh,
                float* __restrict__ ys) {
    extern __shared__ float sm[];
    float* Ws     = sm;                       // [16][1024]
    float* bias_s = sm + ROWS * KTOT;         // [16]
    float* Gs     = bias_s + ROWS;            // [16][64]
    __shared__ unsigned long long base_s;

    const int tid = threadIdx.x;
    const int cg  = blockIdx.x;               // H-column group: cols [4cg, 4cg+4)

    if (tid == 0) {
        unsigned long long v = ld_vol_u64(&g_bar);
        base_s = (v / BAR_PER_LAUNCH) * BAR_PER_LAUNCH;
    }

    // ---- Load this CTA's 16 gate rows of [W_ih | W_hh] into smem (once) ----
    for (int i = tid; i < ROWS * (KTOT / 4); i += NTHREADS) {
        const int r  = i >> 8;                // 256 float4 per row
        const int kq = i & 255;
        const int k  = kq << 2;
        const int g = r >> 2, c = r & 3;
        const int grow = g * HID + (cg << 2) + c;
        float4 v;
        if (k < INP) v = *(const float4*)(W_ih + (size_t)grow * INP + k);
        else         v = *(const float4*)(W_hh + (size_t)grow * HID + (k - INP));
        *(float4*)(Ws + (size_t)r * KTOT + k) = v;
    }
    if (tid < ROWS) {
        const int g = tid >> 2, c = tid & 3;
        const int grow = g * HID + (cg << 2) + c;
        bias_s[tid] = b_ih[grow] + b_hh[grow];
    }
    __syncthreads();

    const int warp = tid >> 5, lane = tid & 31;
    const int b0 = (warp >> 1) * 16;          // 4 batch groups of 16
    const int r0 = (warp & 1) * 8;            // 2 row groups of 8
    const int kl = lane * 4;                  // lane-contiguous 16B k-slice

    // update-phase mapping: thread <-> (batch, local col)
    const int ub = tid & 63;
    const int uc = tid >> 6;                  // 0..3
    float c_state = 0.f;

    const unsigned long long my_base = ld_vol_u64(&g_bar); (void)my_base; // no-op warmup
    __syncthreads();
    const unsigned long long base = base_s;

    for (int t = 0; t < T_STEPS; ++t) {
        float red[128];
        #pragma unroll
        for (int i = 0; i < 128; i++) red[i] = 0.f;

        const float* xt = x + (size_t)t * BATCH * INP;

        // x-projection part: k in [0, 512)
        #pragma unroll
        for (int it = 0; it < 4; ++it) {
            const int k = it * 128 + kl;
            do_iter_x(xt + (size_t)b0 * INP + k, Ws + (size_t)r0 * KTOT + k, red);
        }
        // recurrent part: k in [512, 1024), h_prev = ys[t-1]
        if (t > 0) {
            const float* hprev = ys + (size_t)(t - 1) * BATCH * HID;
            #pragma unroll
            for (int it = 0; it < 4; ++it) {
                const int k = it * 128 + kl;
                do_iter_h(hprev + (size_t)b0 * HID + k,
                          Ws + (size_t)r0 * KTOT + INP + k, red);
            }
        }

        // ---- reduce-scatter butterfly over the 32 lane k-slices ----
        #pragma unroll
        for (int rnd = 0; rnd < 5; rnd++) {
            const int m = 16 >> rnd;
            const int n = 128 >> rnd;
            #pragma unroll
            for (int j = 0; j < 64; j++) {
                if (j < n / 2) {
                    const float lo = red[j], hi = red[j + n / 2];
                    const bool up = (lane & m) != 0;
                    const float mine = up ? hi : lo;
                    const float send = up ? lo : hi;
                    const float recv = __shfl_xor_sync(0xffffffffu, send, m);
                    red[j] = mine + recv;
                }
            }
        }
        // lane owns outputs (b' = lane>>1, r' = 4*(lane&1)+j), j=0..3
        {
            const int bb = b0 + (lane >> 1);
            const int rb = r0 + ((lane & 1) << 2);
            #pragma unroll
            for (int j = 0; j < 4; j++) Gs[(rb + j) * BATCH + bb] = red[j];
        }
        __syncthreads();

        // ---- gate activation + state update (thread = one (b, col)) ----
        {
            const float gi = Gs[(0 * 4 + uc) * BATCH + ub] + bias_s[0 * 4 + uc];
            const float gf = Gs[(1 * 4 + uc) * BATCH + ub] + bias_s[1 * 4 + uc];
            const float gg = Gs[(2 * 4 + uc) * BATCH + ub] + bias_s[2 * 4 + uc];
            const float go = Gs[(3 * 4 + uc) * BATCH + ub] + bias_s[3 * 4 + uc];
            const float i_g = 1.f / (1.f + expf(-gi));
            const float f_g = 1.f / (1.f + expf(-gf));
            const float g_g = tanhf(gg);
            const float o_g = 1.f / (1.f + expf(-go));
            c_state = f_g * c_state + i_g * g_g;
            const float h = o_g * tanhf(c_state);
            ys[((size_t)t * BATCH + ub) * HID + (cg << 2) + uc] = h;
        }

        // ---- grid barrier (monotonic counter, leader-spins pattern) ----
        __syncthreads();          // Gs reads done; local h stores issued
        __threadfence();          // publish h to L2 before signaling
        if (tid == 0) {
            atomicAdd(&g_bar, 1ULL);
            const unsigned long long target = base + (unsigned long long)(t + 1) * NCTA;
            while (ld_vol_u64(&g_bar) < target) { __nanosleep(64); }
            __threadfence();
        }
        __syncthreads();
    }
}

extern "C" void kernel_launch(void* const* d_in, const int* in_sizes, int n_in,
                              void* d_out, int out_size) {
    (void)in_sizes; (void)n_in; (void)out_size;
    const float* x    = (const float*)d_in[0];
    const float* W_ih = (const float*)d_in[1];
    const float* W_hh = (const float*)d_in[2];
    const float* b_ih = (const float*)d_in[3];
    const float* b_hh = (const float*)d_in[4];
    float* ys = (float*)d_out;

    cudaFuncSetAttribute(lstm_persistent,
                         cudaFuncAttributeMaxDynamicSharedMemorySize, SMEM_BYTES);
    lstm_persistent<<<NCTA, NTHREADS, SMEM_BYTES>>>(x, W_ih, W_hh, b_ih, b_hh, ys);
}

// round 7
// speedup vs baseline: 1.2206x; 1.2206x over previous
#include <cuda_runtime.h>
#include <cuda_bf16.h>
#include <cstdint>
#include <cstddef>

// ---------------------------------------------------------------------------
// LSTM T=512 B=64 I=H=512 on sm_103 (no tcgen05): mma.sync bf16 hi/lo split.
//   cvt:   x, W_ih -> bf16 hi/lo scratch
//   xproj: x_projT[2048][32768] = W_ih @ x^T   (3-product bf16 split, fp32 acc)
//   rec:   persistent 128-CTA recurrence with grid barrier
// ---------------------------------------------------------------------------

#define T_STEPS 512
#define BATCH   64
#define HID     512
#define TB      32768              // T*B
#define NROWS   2048               // 4*H gate rows

__device__ __align__(16) __nv_bfloat16 g_xhi[(size_t)TB * HID];
__device__ __align__(16) __nv_bfloat16 g_xlo[(size_t)TB * HID];
__device__ __align__(16) __nv_bfloat16 g_whi[(size_t)NROWS * HID];
__device__ __align__(16) __nv_bfloat16 g_wlo[(size_t)NROWS * HID];
__device__ __align__(16) float         g_xpT[(size_t)NROWS * TB];   // [m][tb]
__device__ __align__(16) __nv_bfloat16 g_hhi[2][32 * HID];          // h image per half
__device__ __align__(16) __nv_bfloat16 g_hlo[2][32 * HID];
__device__ unsigned long long g_bar = 0ull;

#define REC_NCTA 128
#define BARS_PER_LAUNCH (511ull * REC_NCTA)

// ------------------------------ helpers ------------------------------------
__device__ __forceinline__ unsigned long long ld_vol_u64(const unsigned long long* p) {
    unsigned long long v;
    asm volatile("ld.volatile.global.u64 %0, [%1];" : "=l"(v) : "l"(p));
    return v;
}
__device__ __forceinline__ uint32_t ld_s32(const char* p) {
    return *reinterpret_cast<const uint32_t*>(p);
}
__device__ __forceinline__ void mma_bf16(float (&d)[4], const uint32_t (&a)[4],
                                         const uint32_t (&b)[2]) {
    asm volatile(
        "mma.sync.aligned.m16n8k16.row.col.f32.bf16.bf16.f32 "
        "{%0,%1,%2,%3}, {%4,%5,%6,%7}, {%8,%9}, {%0,%1,%2,%3};\n"
        : "+f"(d[0]), "+f"(d[1]), "+f"(d[2]), "+f"(d[3])
        : "r"(a[0]), "r"(a[1]), "r"(a[2]), "r"(a[3]), "r"(b[0]), "r"(b[1]));
}
// A fragment: rows {r, r+8}, k cols {2tq, 2tq+1, +8} (k-major smem, byte stride S)
__device__ __forceinline__ void ldA(uint32_t (&a)[4], const char* base, int row,
                                    int colb, int S) {
    a[0] = ld_s32(base + (size_t)row * S + colb);
    a[1] = ld_s32(base + (size_t)(row + 8) * S + colb);
    a[2] = ld_s32(base + (size_t)row * S + colb + 16);
    a[3] = ld_s32(base + (size_t)(row + 8) * S + colb + 16);
}
__device__ __forceinline__ void ldB(uint32_t (&b)[2], const char* base, int nrow,
                                    int colb, int S) {
    b[0] = ld_s32(base + (size_t)nrow * S + colb);
    b[1] = ld_s32(base + (size_t)nrow * S + colb + 16);
}
__device__ __forceinline__ float fast_sigmoid(float x) { return 1.f / (1.f + __expf(-x)); }
__device__ __forceinline__ float fast_tanh(float x) {
    float ax = fabsf(x);
    float t = 1.f - 2.f / (__expf(2.f * ax) + 1.f);
    return copysignf(t, x);
}

// ===========================================================================
// Kernel 0: fp32 -> bf16 hi/lo conversion for x and W_ih
// ===========================================================================
__global__ void cvt_kernel(const float* __restrict__ x, const float* __restrict__ W_ih) {
    const size_t stride = (size_t)gridDim.x * blockDim.x;
    const size_t gid = (size_t)blockIdx.x * blockDim.x + threadIdx.x;
    for (size_t i = gid; i < (size_t)NROWS * HID; i += stride) {
        float v = W_ih[i];
        __nv_bfloat16 h = __float2bfloat16(v);
        g_whi[i] = h;
        g_wlo[i] = __float2bfloat16(v - __bfloat162float(h));
    }
    for (size_t i = gid; i < (size_t)TB * HID; i += stride) {
        float v = x[i];
        __nv_bfloat16 h = __float2bfloat16(v);
        g_xhi[i] = h;
        g_xlo[i] = __float2bfloat16(v - __bfloat162float(h));
    }
}

// ===========================================================================
// Kernel 1: x_projT = W_ih @ X^T.  CTA tile M128 x N128, K-chunks of 64,
// cp.async double buffer. 16 warps, warp tile 32x32. 3-product split.
// smem row: 64 k + 8 pad = 72 elems = 144 B.
// ===========================================================================
#define KC 64
#define S1 144
#define PART1 (128 * S1)       // 18432 B per part tile
#define BUFSZ (4 * PART1)      // A_hi A_lo B_hi B_lo
#define SMEM1 (2 * BUFSZ)      // 147456 B

__device__ __forceinline__ void xp_issue(char* smc, int c, int m0, int n0, int tid) {
    const int buf = c & 1;
    const int kb = c * KC;
    char* base = smc + buf * BUFSZ;
    #pragma unroll
    for (int j = 0; j < 8; j++) {
        const int id = j * 512 + tid;
        const int which = id >> 10;        // 0 A_hi, 1 A_lo, 2 B_hi, 3 B_lo
        const int r = (id >> 3) & 127;
        const int s = id & 7;
        const __nv_bfloat16* src;
        if (which == 0)      src = g_whi + (size_t)(m0 + r) * HID + kb + s * 8;
        else if (which == 1) src = g_wlo + (size_t)(m0 + r) * HID + kb + s * 8;
        else if (which == 2) src = g_xhi + (size_t)(n0 + r) * HID + kb + s * 8;
        else                 src = g_xlo + (size_t)(n0 + r) * HID + kb + s * 8;
        const uint32_t dst =
            (uint32_t)__cvta_generic_to_shared(base + which * PART1 + r * S1 + s * 16);
        asm volatile("cp.async.cg.shared.global [%0], [%1], 16;\n" :: "r"(dst), "l"(src));
    }
    asm volatile("cp.async.commit_group;\n" ::: "memory");
}

__global__ void __launch_bounds__(512, 1) xproj_kernel() {
    extern __shared__ char smc[];
    const int tid = threadIdx.x;
    const int mt = blockIdx.x & 15, nt = blockIdx.x >> 4;
    const int m0 = mt * 128, n0 = nt * 128;
    const int warp = tid >> 5, lane = tid & 31;
    const int wm = warp >> 2, wn = warp & 3;       // 4x4 warp grid of 32x32
    const int g = lane >> 2, tq = lane & 3;

    float acc[2][4][4];
    #pragma unroll
    for (int mi = 0; mi < 2; mi++)
        #pragma unroll
        for (int ni = 0; ni < 4; ni++)
            #pragma unroll
            for (int q = 0; q < 4; q++) acc[mi][ni][q] = 0.f;

    xp_issue(smc, 0, m0, n0, tid);

    for (int c = 0; c < 8; c++) {
        if (c < 7) {
            xp_issue(smc, c + 1, m0, n0, tid);
            asm volatile("cp.async.wait_group %0;\n" :: "n"(1) : "memory");
        } else {
            asm volatile("cp.async.wait_group %0;\n" :: "n"(0) : "memory");
        }
        __syncthreads();

        const char* Ah = smc + (c & 1) * BUFSZ;
        const char* Al = Ah + PART1;
        const char* Bh = Al + PART1;
        const char* Bl = Bh + PART1;

        #pragma unroll
        for (int k16 = 0; k16 < 4; k16++) {
            const int colb = (k16 * 16 + 2 * tq) * 2;
            uint32_t aH[2][4], aL[2][4], bH[4][2], bL[4][2];
            #pragma unroll
            for (int mi = 0; mi < 2; mi++) ldA(aH[mi], Ah, wm * 32 + mi * 16 + g, colb, S1);
            #pragma unroll
            for (int ni = 0; ni < 4; ni++) ldB(bH[ni], Bh, wn * 32 + ni * 8 + g, colb, S1);
            #pragma unroll
            for (int mi = 0; mi < 2; mi++)
                #pragma unroll
                for (int ni = 0; ni < 4; ni++) mma_bf16(acc[mi][ni], aH[mi], bH[ni]);
            #pragma unroll
            for (int mi = 0; mi < 2; mi++) ldA(aL[mi], Al, wm * 32 + mi * 16 + g, colb, S1);
            #pragma unroll
            for (int mi = 0; mi < 2; mi++)
                #pragma unroll
                for (int ni = 0; ni < 4; ni++) mma_bf16(acc[mi][ni], aL[mi], bH[ni]);
            #pragma unroll
            for (int ni = 0; ni < 4; ni++) ldB(bL[ni], Bl, wn * 32 + ni * 8 + g, colb, S1);
            #pragma unroll
            for (int mi = 0; mi < 2; mi++)
                #pragma unroll
                for (int ni = 0; ni < 4; ni++) mma_bf16(acc[mi][ni], aH[mi], bL[ni]);
        }
        __syncthreads();
    }

    // epilogue: D(m, n) -> g_xpT[m][n]
    #pragma unroll
    for (int mi = 0; mi < 2; mi++) {
        const int m = m0 + wm * 32 + mi * 16 + g;
        #pragma unroll
        for (int ni = 0; ni < 4; ni++) {
            const int n = n0 + wn * 32 + ni * 8 + 2 * tq;
            float2 v01 = make_float2(acc[mi][ni][0], acc[mi][ni][1]);
            float2 v23 = make_float2(acc[mi][ni][2], acc[mi][ni][3]);
            *(float2*)(g_xpT + (size_t)m * TB + n) = v01;
            *(float2*)(g_xpT + (size_t)(m + 8) * TB + n) = v23;
        }
    }
}

// ===========================================================================
// Kernel 2: recurrence. 128 CTAs = 64 col-groups x 2 batch-halves, 128 thr.
// CTA owns packed rows r=gate*8+c (32 rows) of W_hh, all K=512 in smem hi/lo.
// 4 warps K-split (128 each), partials reduced in smem, activations fused.
// Weight/B smem row stride: 512 k + 8 pad = 520 elems = 1040 B.
// Partial buffer stride: 34 floats (EVEN -> float2 stores stay 8B-aligned).
// ===========================================================================
#define S2 1040
#define OFF_WHI  0
#define OFF_WLO  33280
#define OFF_HHI  66560
#define OFF_HLO  99840
#define OFF_P    133120      // 4 warps x 32 rows x 34 floats = 17408 B
#define OFF_HS   150528      // 32 x 8 floats = 1024 B
#define OFF_BIAS 151552      // 32 floats (128 B)
#define OFF_BASE 151680
#define SMEM2    151808

__global__ void __launch_bounds__(128, 1)
rec_kernel(const float* __restrict__ W_hh, const float* __restrict__ b_ih,
           const float* __restrict__ b_hh, float* __restrict__ ys) {
    extern __shared__ char smc[];
    const int tid = threadIdx.x;
    const int cg = blockIdx.x >> 1, bh = blockIdx.x & 1;
    const int warp = tid >> 5, lane = tid & 31;
    const int g = lane >> 2, tq = lane & 3;

    float* Pb     = (float*)(smc + OFF_P);
    float* Hs     = (float*)(smc + OFF_HS);
    float* bias_s = (float*)(smc + OFF_BIAS);

    if (tid == 0) {
        unsigned long long v = ld_vol_u64(&g_bar);
        *(unsigned long long*)(smc + OFF_BASE) = (v / BARS_PER_LAUNCH) * BARS_PER_LAUNCH;
    }
    // load + split W_hh rows (once)
    for (int i = tid; i < 32 * 512; i += 128) {
        const int r = i >> 9, k = i & 511;
        const int grow = (r >> 3) * HID + cg * 8 + (r & 7);
        float v = __ldg(W_hh + (size_t)grow * HID + k);
        __nv_bfloat16 h = __float2bfloat16(v);
        *(__nv_bfloat16*)(smc + OFF_WHI + (size_t)r * S2 + k * 2) = h;
        *(__nv_bfloat16*)(smc + OFF_WLO + (size_t)r * S2 + k * 2) =
            __float2bfloat16(v - __bfloat162float(h));
    }
    if (tid < 32) {
        const int grow = (tid >> 3) * HID + cg * 8 + (tid & 7);
        bias_s[tid] = __ldg(b_ih + grow) + __ldg(b_hh + grow);
    }
    __syncthreads();
    const unsigned long long base = *(const unsigned long long*)(smc + OFF_BASE);

    const int cA = tid >> 5;    // c for pair 0; pair 1 uses cA+4
    const int bb = tid & 31;    // batch within half
    float cst[2] = {0.f, 0.f};

    for (int t = 0; t < T_STEPS; t++) {
        // prefetch x_proj (overlaps image copy + GEMM)
        float xp[2][4];
        {
            const size_t ncol = (size_t)t * 64 + bh * 32 + bb;
            #pragma unroll
            for (int gate = 0; gate < 4; gate++) {
                xp[0][gate] = __ldg(g_xpT + (size_t)(gate * HID + cg * 8 + cA) * TB + ncol);
                xp[1][gate] = __ldg(g_xpT + (size_t)(gate * HID + cg * 8 + cA + 4) * TB + ncol);
            }
        }

        if (t > 0) {
            // h image (hi+lo, 64 KB) L2 -> smem
            #pragma unroll
            for (int j = 0; j < 32; j++) {
                const int id = j * 128 + tid;
                const int part = id >> 11, r = (id >> 6) & 31, s = id & 63;
                const uint4* src =
                    (const uint4*)((part ? g_hlo[bh] : g_hhi[bh]) + (size_t)r * HID) + s;
                uint4 v = __ldcg(src);
                *(uint4*)(smc + (part ? OFF_HLO : OFF_HHI) + (size_t)r * S2 + s * 16) = v;
            }
            __syncthreads();

            // warp GEMM on its 128-k slice, 3 products
            float acc[2][4][4];
            #pragma unroll
            for (int mi = 0; mi < 2; mi++)
                #pragma unroll
                for (int ni = 0; ni < 4; ni++)
                    #pragma unroll
                    for (int q = 0; q < 4; q++) acc[mi][ni][q] = 0.f;

            const char* Wh = smc + OFF_WHI;
            const char* Wl = smc + OFF_WLO;
            const char* Bh = smc + OFF_HHI;
            const char* Bl = smc + OFF_HLO;
            const int k0 = warp * 128;
            #pragma unroll
            for (int kc = 0; kc < 8; kc++) {
                const int colb = (k0 + kc * 16 + 2 * tq) * 2;
                uint32_t aH[2][4], aL[2][4], bH[4][2], bL[4][2];
                #pragma unroll
                for (int mi = 0; mi < 2; mi++) ldA(aH[mi], Wh, mi * 16 + g, colb, S2);
                #pragma unroll
                for (int ni = 0; ni < 4; ni++) ldB(bH[ni], Bh, ni * 8 + g, colb, S2);
                #pragma unroll
                for (int mi = 0; mi < 2; mi++)
                    #pragma unroll
                    for (int ni = 0; ni < 4; ni++) mma_bf16(acc[mi][ni], aH[mi], bH[ni]);
                #pragma unroll
                for (int mi = 0; mi < 2; mi++) ldA(aL[mi], Wl, mi * 16 + g, colb, S2);
                #pragma unroll
                for (int mi = 0; mi < 2; mi++)
                    #pragma unroll
                    for (int ni = 0; ni < 4; ni++) mma_bf16(acc[mi][ni], aL[mi], bH[ni]);
                #pragma unroll
                for (int ni = 0; ni < 4; ni++) ldB(bL[ni], Bl, ni * 8 + g, colb, S2);
                #pragma unroll
                for (int mi = 0; mi < 2; mi++)
                    #pragma unroll
                    for (int ni = 0; ni < 4; ni++) mma_bf16(acc[mi][ni], aH[mi], bL[ni]);
            }
            // partial stores P[warp][m][n] (n-stride 34, even -> aligned float2)
            #pragma unroll
            for (int mi = 0; mi < 2; mi++) {
                #pragma unroll
                for (int ni = 0; ni < 4; ni++) {
                    const int m = mi * 16 + g;
                    const int n = ni * 8 + 2 * tq;
                    *(float2*)(Pb + (size_t)(warp * 32 + m) * 34 + n) =
                        make_float2(acc[mi][ni][0], acc[mi][ni][1]);
                    *(float2*)(Pb + (size_t)(warp * 32 + m + 8) * 34 + n) =
                        make_float2(acc[mi][ni][2], acc[mi][ni][3]);
                }
            }
            __syncthreads();
        }

        // activations: thread handles (cA, bb) and (cA+4, bb)
        #pragma unroll
        for (int p = 0; p < 2; p++) {
            const int c = cA + p * 4;
            float gv[4];
            #pragma unroll
            for (int gate = 0; gate < 4; gate++) {
                float s = xp[p][gate] + bias_s[gate * 8 + c];
                if (t > 0) {
                    #pragma unroll
                    for (int w = 0; w < 4; w++)
                        s += Pb[(size_t)(w * 32 + gate * 8 + c) * 34 + bb];
                }
                gv[gate] = s;
            }
            const float ig = fast_sigmoid(gv[0]);
            const float fg = fast_sigmoid(gv[1]);
            const float gg = fast_tanh(gv[2]);
            const float og = fast_sigmoid(gv[3]);
            cst[p] = fg * cst[p] + ig * gg;
            Hs[bb * 8 + c] = og * fast_tanh(cst[p]);
        }
        __syncthreads();

        // publish h: ys (float4) + bf16 hi/lo images (uint4 via aligned union)
        if (tid < 64) {
            const int b = tid >> 1, half = tid & 1;
            float4 v = *(float4*)(Hs + b * 8 + half * 4);
            *(float4*)(ys + ((size_t)t * 64 + bh * 32 + b) * HID + cg * 8 + half * 4) = v;
        }
        if (tid < 32) {
            const int b = tid;
            union { __nv_bfloat162 h2[4]; uint4 v; } uhi, ulo;
            #pragma unroll
            for (int q = 0; q < 4; q++) {
                float v0 = Hs[b * 8 + q * 2], v1 = Hs[b * 8 + q * 2 + 1];
                __nv_bfloat16 h0 = __float2bfloat16(v0), h1 = __float2bfloat16(v1);
                uhi.h2[q].x = h0; uhi.h2[q].y = h1;
                ulo.h2[q].x = __float2bfloat16(v0 - __bfloat162float(h0));
                ulo.h2[q].y = __float2bfloat16(v1 - __bfloat162float(h1));
            }
            *(uint4*)(g_hhi[bh] + (size_t)b * HID + cg * 8) = uhi.v;
            *(uint4*)(g_hlo[bh] + (size_t)b * HID + cg * 8) = ulo.v;
        }

        if (t < T_STEPS - 1) {
            __syncthreads();
            __threadfence();
            if (tid == 0) {
                atomicAdd(&g_bar, 1ull);
                const unsigned long long tgt =
                    base + (unsigned long long)(t + 1) * REC_NCTA;
                while (ld_vol_u64(&g_bar) < tgt) { __nanosleep(32); }
                __threadfence();
            }
            __syncthreads();
        }
    }
}

// ===========================================================================
extern "C" void kernel_launch(void* const* d_in, const int* in_sizes, int n_in,
                              void* d_out, int out_size) {
    (void)in_sizes; (void)n_in; (void)out_size;
    const float* x    = (const float*)d_in[0];
    const float* W_ih = (const float*)d_in[1];
    const float* W_hh = (const float*)d_in[2];
    const float* b_ih = (const float*)d_in[3];
    const float* b_hh = (const float*)d_in[4];
    float* ys = (float*)d_out;

    cudaFuncSetAttribute(xproj_kernel, cudaFuncAttributeMaxDynamicSharedMemorySize, SMEM1);
    cudaFuncSetAttribute(rec_kernel,   cudaFuncAttributeMaxDynamicSharedMemorySize, SMEM2);

    cvt_kernel<<<2048, 256>>>(x, W_ih);
    xproj_kernel<<<4096, 512, SMEM1>>>();
    rec_kernel<<<REC_NCTA, 128, SMEM2>>>(W_hh, b_ih, b_hh, ys);
}

// round 8
// speedup vs baseline: 1.7821x; 1.4600x over previous
#include <cuda_runtime.h>
#include <cuda_bf16.h>
#include <cstdint>
#include <cstddef>

// ---------------------------------------------------------------------------
// LSTM T=512 B=64 I=H=512 on sm_103 (no tcgen05): mma.sync bf16 hi/lo split.
//   cvt:   x, W_ih -> bf16 hi/lo scratch
//   xproj: x_projT[2048][32768] = W_ih @ x^T   (3-product bf16 split, fp32 acc)
//   rec:   persistent 128-CTA recurrence, 256 thr, warp-sliced image copy
// ---------------------------------------------------------------------------

#define T_STEPS 512
#define BATCH   64
#define HID     512
#define TB      32768              // T*B
#define NROWS   2048               // 4*H gate rows

__device__ __align__(16) __nv_bfloat16 g_xhi[(size_t)TB * HID];
__device__ __align__(16) __nv_bfloat16 g_xlo[(size_t)TB * HID];
__device__ __align__(16) __nv_bfloat16 g_whi[(size_t)NROWS * HID];
__device__ __align__(16) __nv_bfloat16 g_wlo[(size_t)NROWS * HID];
__device__ __align__(16) float         g_xpT[(size_t)NROWS * TB];   // [m][tb]
__device__ __align__(16) __nv_bfloat16 g_hhi[2][32 * HID];          // h image per half
__device__ __align__(16) __nv_bfloat16 g_hlo[2][32 * HID];
__device__ unsigned long long g_bar = 0ull;

#define REC_NCTA 128
#define BARS_PER_LAUNCH (511ull * REC_NCTA)

// ------------------------------ helpers ------------------------------------
__device__ __forceinline__ unsigned long long ld_vol_u64(const unsigned long long* p) {
    unsigned long long v;
    asm volatile("ld.volatile.global.u64 %0, [%1];" : "=l"(v) : "l"(p));
    return v;
}
__device__ __forceinline__ uint32_t ld_s32(const char* p) {
    return *reinterpret_cast<const uint32_t*>(p);
}
__device__ __forceinline__ void mma_bf16(float (&d)[4], const uint32_t (&a)[4],
                                         const uint32_t (&b)[2]) {
    asm volatile(
        "mma.sync.aligned.m16n8k16.row.col.f32.bf16.bf16.f32 "
        "{%0,%1,%2,%3}, {%4,%5,%6,%7}, {%8,%9}, {%0,%1,%2,%3};\n"
        : "+f"(d[0]), "+f"(d[1]), "+f"(d[2]), "+f"(d[3])
        : "r"(a[0]), "r"(a[1]), "r"(a[2]), "r"(a[3]), "r"(b[0]), "r"(b[1]));
}
// A fragment: rows {r, r+8}, k cols {2tq, 2tq+1, +8} (k-major smem, byte stride S)
__device__ __forceinline__ void ldA(uint32_t (&a)[4], const char* base, int row,
                                    int colb, int S) {
    a[0] = ld_s32(base + (size_t)row * S + colb);
    a[1] = ld_s32(base + (size_t)(row + 8) * S + colb);
    a[2] = ld_s32(base + (size_t)row * S + colb + 16);
    a[3] = ld_s32(base + (size_t)(row + 8) * S + colb + 16);
}
__device__ __forceinline__ void ldB(uint32_t (&b)[2], const char* base, int nrow,
                                    int colb, int S) {
    b[0] = ld_s32(base + (size_t)nrow * S + colb);
    b[1] = ld_s32(base + (size_t)nrow * S + colb + 16);
}
__device__ __forceinline__ float fast_sigmoid(float x) { return 1.f / (1.f + __expf(-x)); }
__device__ __forceinline__ float fast_tanh(float x) {
    float ax = fabsf(x);
    float t = 1.f - 2.f / (__expf(2.f * ax) + 1.f);
    return copysignf(t, x);
}

// ===========================================================================
// Kernel 0: fp32 -> bf16 hi/lo conversion for x and W_ih
// ===========================================================================
__global__ void cvt_kernel(const float* __restrict__ x, const float* __restrict__ W_ih) {
    const size_t stride = (size_t)gridDim.x * blockDim.x;
    const size_t gid = (size_t)blockIdx.x * blockDim.x + threadIdx.x;
    for (size_t i = gid; i < (size_t)NROWS * HID; i += stride) {
        float v = W_ih[i];
        __nv_bfloat16 h = __float2bfloat16(v);
        g_whi[i] = h;
        g_wlo[i] = __float2bfloat16(v - __bfloat162float(h));
    }
    for (size_t i = gid; i < (size_t)TB * HID; i += stride) {
        float v = x[i];
        __nv_bfloat16 h = __float2bfloat16(v);
        g_xhi[i] = h;
        g_xlo[i] = __float2bfloat16(v - __bfloat162float(h));
    }
}

// ===========================================================================
// Kernel 1: x_projT = W_ih @ X^T.  CTA tile M128 x N128, K-chunks of 64,
// cp.async double buffer. 16 warps, warp tile 32x32. 3-product split.
// smem row: 64 k + 8 pad = 72 elems = 144 B.
// ===========================================================================
#define KC 64
#define S1 144
#define PART1 (128 * S1)       // 18432 B per part tile
#define BUFSZ (4 * PART1)      // A_hi A_lo B_hi B_lo
#define SMEM1 (2 * BUFSZ)      // 147456 B

__device__ __forceinline__ void xp_issue(char* smc, int c, int m0, int n0, int tid) {
    const int buf = c & 1;
    const int kb = c * KC;
    char* base = smc + buf * BUFSZ;
    #pragma unroll
    for (int j = 0; j < 8; j++) {
        const int id = j * 512 + tid;
        const int which = id >> 10;        // 0 A_hi, 1 A_lo, 2 B_hi, 3 B_lo
        const int r = (id >> 3) & 127;
        const int s = id & 7;
        const __nv_bfloat16* src;
        if (which == 0)      src = g_whi + (size_t)(m0 + r) * HID + kb + s * 8;
        else if (which == 1) src = g_wlo + (size_t)(m0 + r) * HID + kb + s * 8;
        else if (which == 2) src = g_xhi + (size_t)(n0 + r) * HID + kb + s * 8;
        else                 src = g_xlo + (size_t)(n0 + r) * HID + kb + s * 8;
        const uint32_t dst =
            (uint32_t)__cvta_generic_to_shared(base + which * PART1 + r * S1 + s * 16);
        asm volatile("cp.async.cg.shared.global [%0], [%1], 16;\n" :: "r"(dst), "l"(src));
    }
    asm volatile("cp.async.commit_group;\n" ::: "memory");
}

__global__ void __launch_bounds__(512, 1) xproj_kernel() {
    extern __shared__ char smc[];
    const int tid = threadIdx.x;
    const int mt = blockIdx.x & 15, nt = blockIdx.x >> 4;
    const int m0 = mt * 128, n0 = nt * 128;
    const int warp = tid >> 5, lane = tid & 31;
    const int wm = warp >> 2, wn = warp & 3;       // 4x4 warp grid of 32x32
    const int g = lane >> 2, tq = lane & 3;

    float acc[2][4][4];
    #pragma unroll
    for (int mi = 0; mi < 2; mi++)
        #pragma unroll
        for (int ni = 0; ni < 4; ni++)
            #pragma unroll
            for (int q = 0; q < 4; q++) acc[mi][ni][q] = 0.f;

    xp_issue(smc, 0, m0, n0, tid);

    for (int c = 0; c < 8; c++) {
        if (c < 7) {
            xp_issue(smc, c + 1, m0, n0, tid);
            asm volatile("cp.async.wait_group %0;\n" :: "n"(1) : "memory");
        } else {
            asm volatile("cp.async.wait_group %0;\n" :: "n"(0) : "memory");
        }
        __syncthreads();

        const char* Ah = smc + (c & 1) * BUFSZ;
        const char* Al = Ah + PART1;
        const char* Bh = Al + PART1;
        const char* Bl = Bh + PART1;

        #pragma unroll
        for (int k16 = 0; k16 < 4; k16++) {
            const int colb = (k16 * 16 + 2 * tq) * 2;
            uint32_t aH[2][4], aL[2][4], bH[4][2], bL[4][2];
            #pragma unroll
            for (int mi = 0; mi < 2; mi++) ldA(aH[mi], Ah, wm * 32 + mi * 16 + g, colb, S1);
            #pragma unroll
            for (int ni = 0; ni < 4; ni++) ldB(bH[ni], Bh, wn * 32 + ni * 8 + g, colb, S1);
            #pragma unroll
            for (int mi = 0; mi < 2; mi++)
                #pragma unroll
                for (int ni = 0; ni < 4; ni++) mma_bf16(acc[mi][ni], aH[mi], bH[ni]);
            #pragma unroll
            for (int mi = 0; mi < 2; mi++) ldA(aL[mi], Al, wm * 32 + mi * 16 + g, colb, S1);
            #pragma unroll
            for (int mi = 0; mi < 2; mi++)
                #pragma unroll
                for (int ni = 0; ni < 4; ni++) mma_bf16(acc[mi][ni], aL[mi], bH[ni]);
            #pragma unroll
            for (int ni = 0; ni < 4; ni++) ldB(bL[ni], Bl, wn * 32 + ni * 8 + g, colb, S1);
            #pragma unroll
            for (int mi = 0; mi < 2; mi++)
                #pragma unroll
                for (int ni = 0; ni < 4; ni++) mma_bf16(acc[mi][ni], aH[mi], bL[ni]);
        }
        __syncthreads();
    }

    // epilogue: D(m, n) -> g_xpT[m][n]
    #pragma unroll
    for (int mi = 0; mi < 2; mi++) {
        const int m = m0 + wm * 32 + mi * 16 + g;
        #pragma unroll
        for (int ni = 0; ni < 4; ni++) {
            const int n = n0 + wn * 32 + ni * 8 + 2 * tq;
            float2 v01 = make_float2(acc[mi][ni][0], acc[mi][ni][1]);
            float2 v23 = make_float2(acc[mi][ni][2], acc[mi][ni][3]);
            *(float2*)(g_xpT + (size_t)m * TB + n) = v01;
            *(float2*)(g_xpT + (size_t)(m + 8) * TB + n) = v23;
        }
    }
}

// ===========================================================================
// Kernel 2: recurrence. 128 CTAs = 64 col-groups x 2 batch-halves, 256 thr.
// CTA owns packed rows r=gate*8+c (32 rows) of W_hh, all K=512 in smem hi/lo.
// 8 warps K-split (64 each). Each warp copies ONLY its own k-slice of the h
// image (self-synchronized via syncwarp), so copy overlaps GEMM across warps.
// Weight/B smem row stride: 512 k + 8 pad = 520 elems = 1040 B.
// ===========================================================================
#define S2 1040
#define OFF_WHI  0
#define OFF_WLO  33280
#define OFF_HHI  66560
#define OFF_HLO  99840
#define OFF_P    133120      // 8 warps x 32 rows x 34 floats = 34816 B
#define OFF_HS   167936      // 256 floats = 1024 B
#define OFF_BIAS 168960      // 32 floats (128 B)
#define OFF_BASE 169088
#define SMEM2    169216

__global__ void __launch_bounds__(256, 1)
rec_kernel(const float* __restrict__ W_hh, const float* __restrict__ b_ih,
           const float* __restrict__ b_hh, float* __restrict__ ys) {
    extern __shared__ char smc[];
    const int tid = threadIdx.x;
    const int cg = blockIdx.x >> 1, bh = blockIdx.x & 1;
    const int warp = tid >> 5, lane = tid & 31;
    const int g = lane >> 2, tq = lane & 3;

    float* Pb     = (float*)(smc + OFF_P);
    float* Hs     = (float*)(smc + OFF_HS);
    float* bias_s = (float*)(smc + OFF_BIAS);

    if (tid == 0) {
        unsigned long long v = ld_vol_u64(&g_bar);
        *(unsigned long long*)(smc + OFF_BASE) = (v / BARS_PER_LAUNCH) * BARS_PER_LAUNCH;
    }
    // load + split W_hh rows (once)
    for (int i = tid; i < 32 * 512; i += 256) {
        const int r = i >> 9, k = i & 511;
        const int grow = (r >> 3) * HID + cg * 8 + (r & 7);
        float v = __ldg(W_hh + (size_t)grow * HID + k);
        __nv_bfloat16 h = __float2bfloat16(v);
        *(__nv_bfloat16*)(smc + OFF_WHI + (size_t)r * S2 + k * 2) = h;
        *(__nv_bfloat16*)(smc + OFF_WLO + (size_t)r * S2 + k * 2) =
            __float2bfloat16(v - __bfloat162float(h));
    }
    if (tid < 32) {
        const int grow = (tid >> 3) * HID + cg * 8 + (tid & 7);
        bias_s[tid] = __ldg(b_ih + grow) + __ldg(b_hh + grow);
    }
    __syncthreads();
    const unsigned long long base = *(const unsigned long long*)(smc + OFF_BASE);

    const int cc = tid >> 5;    // hidden col within group (0..7) == warp
    const int bb = tid & 31;    // batch within half
    float cst = 0.f;

    // prefetch x_proj for t=0
    float xpn[4];
    #pragma unroll
    for (int gate = 0; gate < 4; gate++)
        xpn[gate] = __ldg(g_xpT + (size_t)(gate * HID + cg * 8 + cc) * TB + (size_t)bh * 32 + bb);

    const int k0 = warp * 64;   // this warp's k-slice

    for (int t = 0; t < T_STEPS; t++) {
        float xpc[4];
        #pragma unroll
        for (int gate = 0; gate < 4; gate++) xpc[gate] = xpn[gate];

        if (t > 0) {
            // warp copies ONLY its own 64-k slice of the h image (hi+lo)
            #pragma unroll
            for (int img = 0; img < 2; img++) {
                const __nv_bfloat16* srcb = img ? g_hlo[bh] : g_hhi[bh];
                const int offd = img ? OFF_HLO : OFF_HHI;
                #pragma unroll
                for (int j = 0; j < 8; j++) {
                    const int idx = j * 32 + lane;      // 256 uint4 per img slice
                    const int r = idx >> 3;             // batch row 0..31
                    const int kk = k0 + (idx & 7) * 8;  // k (8 bf16 per uint4)
                    uint4 v = __ldcg((const uint4*)(srcb + (size_t)r * HID + kk));
                    *(uint4*)(smc + offd + (size_t)r * S2 + kk * 2) = v;
                }
            }
            __syncwarp();

            // warp GEMM on its 64-k slice, 3 products
            float acc[2][4][4];
            #pragma unroll
            for (int mi = 0; mi < 2; mi++)
                #pragma unroll
                for (int ni = 0; ni < 4; ni++)
                    #pragma unroll
                    for (int q = 0; q < 4; q++) acc[mi][ni][q] = 0.f;

            const char* Wh = smc + OFF_WHI;
            const char* Wl = smc + OFF_WLO;
            const char* Bh = smc + OFF_HHI;
            const char* Bl = smc + OFF_HLO;
            #pragma unroll
            for (int kc = 0; kc < 4; kc++) {
                const int colb = (k0 + kc * 16 + 2 * tq) * 2;
                uint32_t aH[2][4], aL[2][4], bH[4][2], bL[4][2];
                #pragma unroll
                for (int mi = 0; mi < 2; mi++) ldA(aH[mi], Wh, mi * 16 + g, colb, S2);
                #pragma unroll
                for (int ni = 0; ni < 4; ni++) ldB(bH[ni], Bh, ni * 8 + g, colb, S2);
                #pragma unroll
                for (int mi = 0; mi < 2; mi++)
                    #pragma unroll
                    for (int ni = 0; ni < 4; ni++) mma_bf16(acc[mi][ni], aH[mi], bH[ni]);
                #pragma unroll
                for (int mi = 0; mi < 2; mi++) ldA(aL[mi], Wl, mi * 16 + g, colb, S2);
                #pragma unroll
                for (int mi = 0; mi < 2; mi++)
                    #pragma unroll
                    for (int ni = 0; ni < 4; ni++) mma_bf16(acc[mi][ni], aL[mi], bH[ni]);
                #pragma unroll
                for (int ni = 0; ni < 4; ni++) ldB(bL[ni], Bl, ni * 8 + g, colb, S2);
                #pragma unroll
                for (int mi = 0; mi < 2; mi++)
                    #pragma unroll
                    for (int ni = 0; ni < 4; ni++) mma_bf16(acc[mi][ni], aH[mi], bL[ni]);
            }
            // partial stores P[warp][m][n] (n-stride 34, even -> aligned float2)
            #pragma unroll
            for (int mi = 0; mi < 2; mi++) {
                #pragma unroll
                for (int ni = 0; ni < 4; ni++) {
                    const int m = mi * 16 + g;
                    const int n = ni * 8 + 2 * tq;
                    *(float2*)(Pb + (size_t)(warp * 32 + m) * 34 + n) =
                        make_float2(acc[mi][ni][0], acc[mi][ni][1]);
                    *(float2*)(Pb + (size_t)(warp * 32 + m + 8) * 34 + n) =
                        make_float2(acc[mi][ni][2], acc[mi][ni][3]);
                }
            }
        }
        __syncthreads();

        // activations: thread = (cc, bb)
        {
            float gv[4];
            #pragma unroll
            for (int gate = 0; gate < 4; gate++) {
                float s = xpc[gate] + bias_s[gate * 8 + cc];
                if (t > 0) {
                    #pragma unroll
                    for (int w = 0; w < 8; w++)
                        s += Pb[(size_t)(w * 32 + gate * 8 + cc) * 34 + bb];
                }
                gv[gate] = s;
            }
            const float ig = fast_sigmoid(gv[0]);
            const float fg = fast_sigmoid(gv[1]);
            const float gg = fast_tanh(gv[2]);
            const float og = fast_sigmoid(gv[3]);
            cst = fg * cst + ig * gg;
            Hs[bb * 8 + cc] = og * fast_tanh(cst);
        }
        __syncthreads();

        // publish bf16 hi/lo h images FIRST (critical path for other CTAs)
        if (tid < 32) {
            const int b = tid;
            union { __nv_bfloat162 h2[4]; uint4 v; } uhi, ulo;
            #pragma unroll
            for (int q = 0; q < 4; q++) {
                float v0 = Hs[b * 8 + q * 2], v1 = Hs[b * 8 + q * 2 + 1];
                __nv_bfloat16 h0 = __float2bfloat16(v0), h1 = __float2bfloat16(v1);
                uhi.h2[q].x = h0; uhi.h2[q].y = h1;
                ulo.h2[q].x = __float2bfloat16(v0 - __bfloat162float(h0));
                ulo.h2[q].y = __float2bfloat16(v1 - __bfloat162float(h1));
            }
            *(uint4*)(g_hhi[bh] + (size_t)b * HID + cg * 8) = uhi.v;
            *(uint4*)(g_hlo[bh] + (size_t)b * HID + cg * 8) = ulo.v;
        }
        __threadfence();
        __syncthreads();

        // arrive ASAP, then overlap ys store + next-xp prefetch with the spin
        if (t < T_STEPS - 1 && tid == 0) atomicAdd(&g_bar, 1ull);

        if (tid < 64) {
            const int b = tid >> 1, half = tid & 1;
            float4 v = *(float4*)(Hs + b * 8 + half * 4);
            *(float4*)(ys + ((size_t)t * 64 + bh * 32 + b) * HID + cg * 8 + half * 4) = v;
        }
        {
            const int tn = (t + 1 < T_STEPS) ? t + 1 : t;
            const size_t ncol = (size_t)tn * 64 + bh * 32 + bb;
            #pragma unroll
            for (int gate = 0; gate < 4; gate++)
                xpn[gate] = __ldg(g_xpT + (size_t)(gate * HID + cg * 8 + cc) * TB + ncol);
        }

        if (t < T_STEPS - 1) {
            if (tid == 0) {
                const unsigned long long tgt =
                    base + (unsigned long long)(t + 1) * REC_NCTA;
                while (ld_vol_u64(&g_bar) < tgt) { __nanosleep(32); }
                __threadfence();
            }
            __syncthreads();
        }
    }
}

// ===========================================================================
extern "C" void kernel_launch(void* const* d_in, const int* in_sizes, int n_in,
                              void* d_out, int out_size) {
    (void)in_sizes; (void)n_in; (void)out_size;
    const float* x    = (const float*)d_in[0];
    const float* W_ih = (const float*)d_in[1];
    const float* W_hh = (const float*)d_in[2];
    const float* b_ih = (const float*)d_in[3];
    const float* b_hh = (const float*)d_in[4];
    float* ys = (float*)d_out;

    cudaFuncSetAttribute(xproj_kernel, cudaFuncAttributeMaxDynamicSharedMemorySize, SMEM1);
    cudaFuncSetAttribute(rec_kernel,   cudaFuncAttributeMaxDynamicSharedMemorySize, SMEM2);

    cvt_kernel<<<2048, 256>>>(x, W_ih);
    xproj_kernel<<<4096, 512, SMEM1>>>();
    rec_kernel<<<REC_NCTA, 256, SMEM2>>>(W_hh, b_ih, b_hh, ys);
}

// round 9
// speedup vs baseline: 2.0060x; 1.1256x over previous
#include <cuda_runtime.h>
#include <cuda_bf16.h>
#include <cstdint>
#include <cstddef>

// ---------------------------------------------------------------------------
// LSTM T=512 B=64 I=H=512 on sm_103 (no tcgen05): mma.sync bf16 hi/lo split.
//   cvt:   x, W_ih -> bf16 hi/lo scratch
//   xproj: x_projT[2048][32768] = W_ih @ x^T   (3-product bf16 split, fp32 acc)
//   rec:   persistent 128-CTA recurrence; reg-resident weights; fragment-
//          ordered double-buffered h image consumed by direct coalesced LDG.
// ---------------------------------------------------------------------------

#define T_STEPS 512
#define BATCH   64
#define HID     512
#define TB      32768              // T*B
#define NROWS   2048               // 4*H gate rows

__device__ __align__(16) __nv_bfloat16 g_xhi[(size_t)TB * HID];
__device__ __align__(16) __nv_bfloat16 g_xlo[(size_t)TB * HID];
__device__ __align__(16) __nv_bfloat16 g_whi[(size_t)NROWS * HID];
__device__ __align__(16) __nv_bfloat16 g_wlo[(size_t)NROWS * HID];
__device__ __align__(16) float         g_xpT[(size_t)NROWS * TB];   // [m][tb]
// fragment-ordered h image: [parity][bh][64KB/4 words]
// word offset = ((wk*4+kc)*2+part)*256 + (ni*2+reg)*32 + lane
__device__ __align__(16) uint32_t g_img[2][2][16384];
__device__ unsigned long long g_bar = 0ull;

#define REC_NCTA 128
#define BARS_PER_LAUNCH (511ull * REC_NCTA)

// ------------------------------ helpers ------------------------------------
__device__ __forceinline__ unsigned long long ld_vol_u64(const unsigned long long* p) {
    unsigned long long v;
    asm volatile("ld.volatile.global.u64 %0, [%1];" : "=l"(v) : "l"(p));
    return v;
}
__device__ __forceinline__ uint32_t ld_s32(const char* p) {
    return *reinterpret_cast<const uint32_t*>(p);
}
__device__ __forceinline__ uint32_t ldcg_u32(const uint32_t* p) {
    uint32_t v;
    asm volatile("ld.global.cg.b32 %0, [%1];" : "=r"(v) : "l"(p));
    return v;
}
__device__ __forceinline__ void mma_bf16(float (&d)[4], const uint32_t (&a)[4],
                                         const uint32_t (&b)[2]) {
    asm volatile(
        "mma.sync.aligned.m16n8k16.row.col.f32.bf16.bf16.f32 "
        "{%0,%1,%2,%3}, {%4,%5,%6,%7}, {%8,%9}, {%0,%1,%2,%3};\n"
        : "+f"(d[0]), "+f"(d[1]), "+f"(d[2]), "+f"(d[3])
        : "r"(a[0]), "r"(a[1]), "r"(a[2]), "r"(a[3]), "r"(b[0]), "r"(b[1]));
}
// A fragment: rows {r, r+8}, k cols {2tq, 2tq+1, +8} (k-major smem, byte stride S)
__device__ __forceinline__ void ldA(uint32_t (&a)[4], const char* base, int row,
                                    int colb, int S) {
    a[0] = ld_s32(base + (size_t)row * S + colb);
    a[1] = ld_s32(base + (size_t)(row + 8) * S + colb);
    a[2] = ld_s32(base + (size_t)row * S + colb + 16);
    a[3] = ld_s32(base + (size_t)(row + 8) * S + colb + 16);
}
__device__ __forceinline__ void ldB(uint32_t (&b)[2], const char* base, int nrow,
                                    int colb, int S) {
    b[0] = ld_s32(base + (size_t)nrow * S + colb);
    b[1] = ld_s32(base + (size_t)nrow * S + colb + 16);
}
__device__ __forceinline__ uint32_t pack_hi2(float2 v) {
    union { __nv_bfloat162 h2; uint32_t u; } r;
    r.h2.x = __float2bfloat16(v.x);
    r.h2.y = __float2bfloat16(v.y);
    return r.u;
}
__device__ __forceinline__ uint32_t pack_lo2(float2 v) {
    union { __nv_bfloat162 h2; uint32_t u; } r;
    __nv_bfloat16 hx = __float2bfloat16(v.x);
    __nv_bfloat16 hy = __float2bfloat16(v.y);
    r.h2.x = __float2bfloat16(v.x - __bfloat162float(hx));
    r.h2.y = __float2bfloat16(v.y - __bfloat162float(hy));
    return r.u;
}
__device__ __forceinline__ float fast_sigmoid(float x) { return 1.f / (1.f + __expf(-x)); }
__device__ __forceinline__ float fast_tanh(float x) {
    float ax = fabsf(x);
    float t = 1.f - 2.f / (__expf(2.f * ax) + 1.f);
    return copysignf(t, x);
}

// ===========================================================================
// Kernel 0: fp32 -> bf16 hi/lo conversion for x and W_ih
// ===========================================================================
__global__ void cvt_kernel(const float* __restrict__ x, const float* __restrict__ W_ih) {
    const size_t stride = (size_t)gridDim.x * blockDim.x;
    const size_t gid = (size_t)blockIdx.x * blockDim.x + threadIdx.x;
    for (size_t i = gid; i < (size_t)NROWS * HID; i += stride) {
        float v = W_ih[i];
        __nv_bfloat16 h = __float2bfloat16(v);
        g_whi[i] = h;
        g_wlo[i] = __float2bfloat16(v - __bfloat162float(h));
    }
    for (size_t i = gid; i < (size_t)TB * HID; i += stride) {
        float v = x[i];
        __nv_bfloat16 h = __float2bfloat16(v);
        g_xhi[i] = h;
        g_xlo[i] = __float2bfloat16(v - __bfloat162float(h));
    }
}

// ===========================================================================
// Kernel 1: x_projT = W_ih @ X^T.  CTA tile M128 x N128, K-chunks of 64,
// cp.async double buffer. 16 warps, warp tile 32x32. 3-product split.
// smem row: 64 k + 8 pad = 72 elems = 144 B.
// ===========================================================================
#define KC 64
#define S1 144
#define PART1 (128 * S1)       // 18432 B per part tile
#define BUFSZ (4 * PART1)      // A_hi A_lo B_hi B_lo
#define SMEM1 (2 * BUFSZ)      // 147456 B

__device__ __forceinline__ void xp_issue(char* smc, int c, int m0, int n0, int tid) {
    const int buf = c & 1;
    const int kb = c * KC;
    char* base = smc + buf * BUFSZ;
    #pragma unroll
    for (int j = 0; j < 8; j++) {
        const int id = j * 512 + tid;
        const int which = id >> 10;        // 0 A_hi, 1 A_lo, 2 B_hi, 3 B_lo
        const int r = (id >> 3) & 127;
        const int s = id & 7;
        const __nv_bfloat16* src;
        if (which == 0)      src = g_whi + (size_t)(m0 + r) * HID + kb + s * 8;
        else if (which == 1) src = g_wlo + (size_t)(m0 + r) * HID + kb + s * 8;
        else if (which == 2) src = g_xhi + (size_t)(n0 + r) * HID + kb + s * 8;
        else                 src = g_xlo + (size_t)(n0 + r) * HID + kb + s * 8;
        const uint32_t dst =
            (uint32_t)__cvta_generic_to_shared(base + which * PART1 + r * S1 + s * 16);
        asm volatile("cp.async.cg.shared.global [%0], [%1], 16;\n" :: "r"(dst), "l"(src));
    }
    asm volatile("cp.async.commit_group;\n" ::: "memory");
}

__global__ void __launch_bounds__(512, 1) xproj_kernel() {
    extern __shared__ char smc[];
    const int tid = threadIdx.x;
    const int mt = blockIdx.x & 15, nt = blockIdx.x >> 4;
    const int m0 = mt * 128, n0 = nt * 128;
    const int warp = tid >> 5, lane = tid & 31;
    const int wm = warp >> 2, wn = warp & 3;       // 4x4 warp grid of 32x32
    const int g = lane >> 2, tq = lane & 3;

    float acc[2][4][4];
    #pragma unroll
    for (int mi = 0; mi < 2; mi++)
        #pragma unroll
        for (int ni = 0; ni < 4; ni++)
            #pragma unroll
            for (int q = 0; q < 4; q++) acc[mi][ni][q] = 0.f;

    xp_issue(smc, 0, m0, n0, tid);

    for (int c = 0; c < 8; c++) {
        if (c < 7) {
            xp_issue(smc, c + 1, m0, n0, tid);
            asm volatile("cp.async.wait_group %0;\n" :: "n"(1) : "memory");
        } else {
            asm volatile("cp.async.wait_group %0;\n" :: "n"(0) : "memory");
        }
        __syncthreads();

        const char* Ah = smc + (c & 1) * BUFSZ;
        const char* Al = Ah + PART1;
        const char* Bh = Al + PART1;
        const char* Bl = Bh + PART1;

        #pragma unroll
        for (int k16 = 0; k16 < 4; k16++) {
            const int colb = (k16 * 16 + 2 * tq) * 2;
            uint32_t aH[2][4], aL[2][4], bH[4][2], bL[4][2];
            #pragma unroll
            for (int mi = 0; mi < 2; mi++) ldA(aH[mi], Ah, wm * 32 + mi * 16 + g, colb, S1);
            #pragma unroll
            for (int ni = 0; ni < 4; ni++) ldB(bH[ni], Bh, wn * 32 + ni * 8 + g, colb, S1);
            #pragma unroll
            for (int mi = 0; mi < 2; mi++)
                #pragma unroll
                for (int ni = 0; ni < 4; ni++) mma_bf16(acc[mi][ni], aH[mi], bH[ni]);
            #pragma unroll
            for (int mi = 0; mi < 2; mi++) ldA(aL[mi], Al, wm * 32 + mi * 16 + g, colb, S1);
            #pragma unroll
            for (int mi = 0; mi < 2; mi++)
                #pragma unroll
                for (int ni = 0; ni < 4; ni++) mma_bf16(acc[mi][ni], aL[mi], bH[ni]);
            #pragma unroll
            for (int ni = 0; ni < 4; ni++) ldB(bL[ni], Bl, wn * 32 + ni * 8 + g, colb, S1);
            #pragma unroll
            for (int mi = 0; mi < 2; mi++)
                #pragma unroll
                for (int ni = 0; ni < 4; ni++) mma_bf16(acc[mi][ni], aH[mi], bL[ni]);
        }
        __syncthreads();
    }

    // epilogue: D(m, n) -> g_xpT[m][n]
    #pragma unroll
    for (int mi = 0; mi < 2; mi++) {
        const int m = m0 + wm * 32 + mi * 16 + g;
        #pragma unroll
        for (int ni = 0; ni < 4; ni++) {
            const int n = n0 + wn * 32 + ni * 8 + 2 * tq;
            float2 v01 = make_float2(acc[mi][ni][0], acc[mi][ni][1]);
            float2 v23 = make_float2(acc[mi][ni][2], acc[mi][ni][3]);
            *(float2*)(g_xpT + (size_t)m * TB + n) = v01;
            *(float2*)(g_xpT + (size_t)(m + 8) * TB + n) = v23;
        }
    }
}

// ===========================================================================
// Kernel 2: recurrence. 128 CTAs = 64 col-groups x 2 batch-halves, 256 thr.
// Weights live in REGISTERS (64 u32/lane, hi+lo). h image is fragment-ordered
// in global (double-buffered by step parity): each LDG.32 is a coalesced 128B
// line that IS an mma B-fragment word. No smem staging in the hot loop.
// smem: partials (8 warps x 32 rows x 34 f) + Hs + bias + base.
// ===========================================================================
#define OFF_P    0           // 34816 B
#define OFF_HS   34816       // 256 floats = 1024 B
#define OFF_BIAS 35840       // 32 floats (128 B)
#define OFF_BASE 35968
#define SMEM2    36096

__global__ void __launch_bounds__(256, 1)
rec_kernel(const float* __restrict__ W_hh, const float* __restrict__ b_ih,
           const float* __restrict__ b_hh, float* __restrict__ ys) {
    extern __shared__ char smc[];
    const int tid = threadIdx.x;
    const int cg = blockIdx.x >> 1, bh = blockIdx.x & 1;
    const int warp = tid >> 5, lane = tid & 31;
    const int g = lane >> 2, tq = lane & 3;

    float* Pb     = (float*)(smc + OFF_P);
    float* Hs     = (float*)(smc + OFF_HS);
    float* bias_s = (float*)(smc + OFF_BIAS);

    if (tid == 0) {
        unsigned long long v = ld_vol_u64(&g_bar);
        *(unsigned long long*)(smc + OFF_BASE) = (v / BARS_PER_LAUNCH) * BARS_PER_LAUNCH;
    }
    if (tid < 32) {
        const int grow = (tid >> 3) * HID + cg * 8 + (tid & 7);
        bias_s[tid] = __ldg(b_ih + grow) + __ldg(b_hh + grow);
    }

    // ---- preload this lane's weight fragments into registers (once) ----
    // aH/aL[kc][mi][q]: rows {mi*16+g, +8}, k = k0 + kc*16 + 2tq (+1), +8
    const int k0 = warp * 64;
    uint32_t aH[4][2][4], aL[4][2][4];
    #pragma unroll
    for (int kc = 0; kc < 4; kc++) {
        const int k = k0 + kc * 16 + 2 * tq;
        #pragma unroll
        for (int mi = 0; mi < 2; mi++) {
            #pragma unroll
            for (int rr = 0; rr < 2; rr++) {
                const int row = mi * 16 + g + rr * 8;
                const int grow = (row >> 3) * HID + cg * 8 + (row & 7);
                float2 v0 = __ldg((const float2*)(W_hh + (size_t)grow * HID + k));
                float2 v1 = __ldg((const float2*)(W_hh + (size_t)grow * HID + k + 8));
                aH[kc][mi][rr]     = pack_hi2(v0);
                aH[kc][mi][2 + rr] = pack_hi2(v1);
                aL[kc][mi][rr]     = pack_lo2(v0);
                aL[kc][mi][2 + rr] = pack_lo2(v1);
            }
        }
    }
    __syncthreads();
    const unsigned long long base = *(const unsigned long long*)(smc + OFF_BASE);

    const int cc = tid >> 5;    // hidden col within group (0..7) == warp
    const int bb = tid & 31;    // batch within half
    float cst = 0.f;

    // producer image indexing for this thread's h value (n=bb, k=cg*8+cc)
    uint32_t pub_off;
    {
        const int k = cg * 8 + cc;
        const int wk = k >> 6, kk = k & 63;
        const int kc = kk >> 4, kpos = kk & 15;
        const int reg = kpos >> 3, r = kpos & 7;
        const int tq2 = r >> 1, hs = r & 1;
        const int ni = bb >> 3, g2 = bb & 7;
        const int lanei = g2 * 4 + tq2;
        // byte offset of the hi (part 0) slot; part 1 is +1024 bytes
        pub_off = (uint32_t)((((wk * 4 + kc) * 2 + 0) * 256 + (ni * 2 + reg) * 32 + lanei) * 4
                             + hs * 2);
    }

    // prefetch x_proj for t=0
    float xpn[4];
    #pragma unroll
    for (int gate = 0; gate < 4; gate++)
        xpn[gate] = __ldg(g_xpT + (size_t)(gate * HID + cg * 8 + cc) * TB + (size_t)bh * 32 + bb);

    for (int t = 0; t < T_STEPS; t++) {
        float xpc[4];
        #pragma unroll
        for (int gate = 0; gate < 4; gate++) xpc[gate] = xpn[gate];

        if (t > 0) {
            // ---- load ALL B fragments directly from the fragment-ordered image
            const uint32_t* img = g_img[(t - 1) & 1][bh];
            uint32_t bH[4][4][2], bL[4][4][2];
            #pragma unroll
            for (int kc = 0; kc < 4; kc++) {
                const uint32_t blk = (uint32_t)(warp * 4 + kc) * 2;
                #pragma unroll
                for (int ni = 0; ni < 4; ni++) {
                    #pragma unroll
                    for (int reg = 0; reg < 2; reg++) {
                        const uint32_t w = (uint32_t)(ni * 2 + reg) * 32 + lane;
                        bH[kc][ni][reg] = ldcg_u32(img + blk * 256 + w);
                        bL[kc][ni][reg] = ldcg_u32(img + (blk + 1) * 256 + w);
                    }
                }
            }

            // ---- pure MMA burst (96 issues, everything register-resident)
            float acc[2][4][4];
            #pragma unroll
            for (int mi = 0; mi < 2; mi++)
                #pragma unroll
                for (int ni = 0; ni < 4; ni++)
                    #pragma unroll
                    for (int q = 0; q < 4; q++) acc[mi][ni][q] = 0.f;

            #pragma unroll
            for (int kc = 0; kc < 4; kc++) {
                #pragma unroll
                for (int mi = 0; mi < 2; mi++)
                    #pragma unroll
                    for (int ni = 0; ni < 4; ni++) mma_bf16(acc[mi][ni], aH[kc][mi], bH[kc][ni]);
                #pragma unroll
                for (int mi = 0; mi < 2; mi++)
                    #pragma unroll
                    for (int ni = 0; ni < 4; ni++) mma_bf16(acc[mi][ni], aL[kc][mi], bH[kc][ni]);
                #pragma unroll
                for (int mi = 0; mi < 2; mi++)
                    #pragma unroll
                    for (int ni = 0; ni < 4; ni++) mma_bf16(acc[mi][ni], aH[kc][mi], bL[kc][ni]);
            }

            // partial stores P[warp][m][n] (n-stride 34, even -> aligned float2)
            #pragma unroll
            for (int mi = 0; mi < 2; mi++) {
                #pragma unroll
                for (int ni = 0; ni < 4; ni++) {
                    const int m = mi * 16 + g;
                    const int n = ni * 8 + 2 * tq;
                    *(float2*)(Pb + (size_t)(warp * 32 + m) * 34 + n) =
                        make_float2(acc[mi][ni][0], acc[mi][ni][1]);
                    *(float2*)(Pb + (size_t)(warp * 32 + m + 8) * 34 + n) =
                        make_float2(acc[mi][ni][2], acc[mi][ni][3]);
                }
            }
        }
        __syncthreads();

        // activations: thread = (cc, bb)
        {
            float gv[4];
            #pragma unroll
            for (int gate = 0; gate < 4; gate++) {
                float s = xpc[gate] + bias_s[gate * 8 + cc];
                if (t > 0) {
                    #pragma unroll
                    for (int w = 0; w < 8; w++)
                        s += Pb[(size_t)(w * 32 + gate * 8 + cc) * 34 + bb];
                }
                gv[gate] = s;
            }
            const float ig = fast_sigmoid(gv[0]);
            const float fg = fast_sigmoid(gv[1]);
            const float gg = fast_tanh(gv[2]);
            const float og = fast_sigmoid(gv[3]);
            cst = fg * cst + ig * gg;
            const float h = og * fast_tanh(cst);
            Hs[bb * 8 + cc] = h;

            // publish h into the fragment-ordered image (parity t&1)
            char* imgc = (char*)g_img[t & 1][bh];
            __nv_bfloat16 hh = __float2bfloat16(h);
            __nv_bfloat16 hl = __float2bfloat16(h - __bfloat162float(hh));
            *(__nv_bfloat16*)(imgc + pub_off)        = hh;   // part 0 (hi)
            *(__nv_bfloat16*)(imgc + pub_off + 1024) = hl;   // part 1 (lo)
        }
        __threadfence();
        __syncthreads();

        // arrive ASAP, then overlap ys store + next-xp prefetch with the spin
        if (t < T_STEPS - 1 && tid == 0) atomicAdd(&g_bar, 1ull);

        if (tid < 64) {
            const int b = tid >> 1, half = tid & 1;
            float4 v = *(float4*)(Hs + b * 8 + half * 4);
            *(float4*)(ys + ((size_t)t * 64 + bh * 32 + b) * HID + cg * 8 + half * 4) = v;
        }
        {
            const int tn = (t + 1 < T_STEPS) ? t + 1 : t;
            const size_t ncol = (size_t)tn * 64 + bh * 32 + bb;
            #pragma unroll
            for (int gate = 0; gate < 4; gate++)
                xpn[gate] = __ldg(g_xpT + (size_t)(gate * HID + cg * 8 + cc) * TB + ncol);
        }

        if (t < T_STEPS - 1) {
            if (tid == 0) {
                const unsigned long long tgt =
                    base + (unsigned long long)(t + 1) * REC_NCTA;
                while (ld_vol_u64(&g_bar) < tgt) { __nanosleep(32); }
                __threadfence();
            }
            __syncthreads();
        }
    }
}

// ===========================================================================
extern "C" void kernel_launch(void* const* d_in, const int* in_sizes, int n_in,
                              void* d_out, int out_size) {
    (void)in_sizes; (void)n_in; (void)out_size;
    const float* x    = (const float*)d_in[0];
    const float* W_ih = (const float*)d_in[1];
    const float* W_hh = (const float*)d_in[2];
    const float* b_ih = (const float*)d_in[3];
    const float* b_hh = (const float*)d_in[4];
    float* ys = (float*)d_out;

    cudaFuncSetAttribute(xproj_kernel, cudaFuncAttributeMaxDynamicSharedMemorySize, SMEM1);
    cudaFuncSetAttribute(rec_kernel,   cudaFuncAttributeMaxDynamicSharedMemorySize, SMEM2);

    cvt_kernel<<<2048, 256>>>(x, W_ih);
    xproj_kernel<<<4096, 512, SMEM1>>>();
    rec_kernel<<<REC_NCTA, 256, SMEM2>>>(W_hh, b_ih, b_hh, ys);
}